// round 15
// baseline (speedup 1.0000x reference)
#include <cuda_runtime.h>
#include <math.h>

#define Jn 21
#define NHn 7
#define Hn 4
#define HDn 64
#define NTHREADS 256
#define HPT_LD 28
#define ATT_LD 28

typedef unsigned long long ull;

// ---- shared memory layout (float offsets) ----
constexpr int OFF_H    = 0;                              // 4*21*64 = 5376 (alias: RED partials in ph3)
constexpr int OFF_HPT  = OFF_H + Hn * Jn * HDn;          // 256*28  = 7168
constexpr int OFF_ATTN = OFF_HPT + 256 * HPT_LD;         // 4*21*28 = 2352 (alias: AT2 in ph4b)
constexpr int OFF_XD   = OFF_ATTN + Hn * Jn * ATT_LD;    // 21*8*2  = 336 (dup f2)
constexpr int OFF_F1   = OFF_XD + Jn * 8 * 2;            // 84
constexpr int OFF_F2   = OFF_F1 + Hn * Jn;               // 84
constexpr int OFF_H2   = OFF_F2 + Hn * Jn;               // 21*64 = 1344
constexpr int OFF_F1B  = OFF_H2 + Jn * HDn;              // 21
constexpr int OFF_F2B  = OFF_F1B + Jn;                   // 21
constexpr int OFF_AT2  = OFF_ATTN;                       // alias (ATTN dead after ph2b)
constexpr int SMEM_FLOATS = OFF_F2B + Jn;                // 16786
constexpr int SMEM_BYTES  = SMEM_FLOATS * 4;             // ~67.1 KB -> 3 CTAs/SM (201 KB)

static_assert(OFF_HPT % 4 == 0 && OFF_ATTN % 4 == 0 && OFF_XD % 4 == 0, "align16");
static_assert(Hn * Jn * HDn == 4 * Jn * 64, "RED fits H exactly");

__device__ __forceinline__ void ffma2(ull& d, ull a, ull b) {
    asm("fma.rn.f32x2 %0, %1, %2, %3;" : "=l"(d) : "l"(a), "l"(b), "l"(d));
}
__device__ __forceinline__ void fadd2(ull& d, ull a, ull b) {
    asm("add.rn.f32x2 %0, %1, %2;" : "=l"(d) : "l"(a), "l"(b));
}
__device__ __forceinline__ ull dup2(float x) {
    ull r; unsigned xi = __float_as_uint(x);
    asm("mov.b64 %0, {%1, %1};" : "=l"(r) : "r"(xi));
    return r;
}
__device__ __forceinline__ ull pack2(float a, float b) {
    ull r;
    asm("mov.b64 %0, {%1, %2};" : "=l"(r) : "f"(a), "f"(b));
    return r;
}
__device__ __forceinline__ float2 unpk(ull v) {
    float2 r;
    asm("mov.b64 {%0, %1}, %2;" : "=f"(r.x), "=f"(r.y) : "l"(v));
    return r;
}
__device__ __forceinline__ float warp_sum(float v) {
    #pragma unroll
    for (int o = 16; o > 0; o >>= 1) v += __shfl_xor_sync(0xffffffffu, v, o);
    return v;
}
__device__ __forceinline__ float warp_max(float v) {
    #pragma unroll
    for (int o = 16; o > 0; o >>= 1) v = fmaxf(v, __shfl_xor_sync(0xffffffffu, v, o));
    return v;
}
__device__ __forceinline__ void warp_sum2(float& a, float& b) {
    #pragma unroll
    for (int o = 16; o > 0; o >>= 1) {
        a += __shfl_xor_sync(0xffffffffu, a, o);
        b += __shfl_xor_sync(0xffffffffu, b, o);
    }
}
__device__ __forceinline__ float elu1(float x) {
    return x > 0.f ? x : (__expf(x) - 1.f);
}

// one attention row (21 coeffs, broadcast) dotted against 21 register-held packed vectors
__device__ __forceinline__ ull att_dot(const float* atp, const ull* hv) {
    const float4* at = (const float4*)atp;
    ull acc = 0ull;
    #pragma unroll
    for (int q = 0; q < 5; q++) {
        float4 a4 = at[q];
        ffma2(acc, dup2(a4.x), hv[q * 4 + 0]);
        ffma2(acc, dup2(a4.y), hv[q * 4 + 1]);
        ffma2(acc, dup2(a4.z), hv[q * 4 + 2]);
        ffma2(acc, dup2(a4.w), hv[q * 4 + 3]);
    }
    ffma2(acc, dup2(atp[20]), hv[20]);
    return acc;
}

__global__ void __launch_bounds__(NTHREADS, 3)
gat_kernel(const float* __restrict__ inp,
           const float* __restrict__ W_heads,
           const float* __restrict__ a_heads,
           const float* __restrict__ W_out,
           const float* __restrict__ a_out,
           float* __restrict__ out)
{
    extern __shared__ float sm[];
    const int tid  = threadIdx.x;
    const int lane = tid & 31;
    const int wid  = tid >> 5;
    const int pair = blockIdx.x;

    // ---------------- Phase 0: stage x (reshaped, duplicated for f32x2) ----------------
    {
        const float* ip = inp + (long long)pair * (Jn * NHn);
        if (tid < Jn * NHn) {
            float v = ip[tid];
            int j, c;
            if (tid < Jn * 3)          { j = tid / 3;          c = tid % 3; }
            else if (tid < 2 * Jn * 3) { int t = tid - Jn * 3; j = t / 3;  c = 3 + t % 3; }
            else                       { j = tid - 2 * Jn * 3; c = 6; }
            ((float2*)(sm + OFF_XD))[j * 8 + c] = make_float2(v, v);
        }
        if (tid < Jn)   // zero pad slot c=7
            ((float2*)(sm + OFF_XD))[tid * 8 + 7] = make_float2(0.f, 0.f);
    }
    __syncthreads();

    // ---------------- Phase 1 (+1b): h = x @ Wh ; f1/f2 = x @ (Wh@a) ----------------
    {
        const int hh = wid >> 1;           // head
        const int jh = wid & 1;            // j-half
        const float* wg = W_heads + hh * (NHn * HDn) + lane;
        ull w[NHn];
        #pragma unroll
        for (int n = 0; n < NHn; n++)
            w[n] = pack2(__ldg(wg + n * HDn), __ldg(wg + n * HDn + 32));
        const float2 a1f = make_float2(__ldg(a_heads + hh * 128 + lane),
                                       __ldg(a_heads + hh * 128 + lane + 32));
        const float2 a2f = make_float2(__ldg(a_heads + hh * 128 + 64 + lane),
                                       __ldg(a_heads + hh * 128 + 64 + lane + 32));
        float wa1[NHn], wa2[NHn];
        #pragma unroll
        for (int n = 0; n < NHn; n++) {
            float2 wf = unpk(w[n]);
            float p1 = wf.x * a1f.x + wf.y * a1f.y;
            float p2 = wf.x * a2f.x + wf.y * a2f.y;
            warp_sum2(p1, p2);
            wa1[n] = p1; wa2[n] = p2;
        }

        const int j0 = jh * 11, cnt = 11 - jh;
        const ulonglong2* xd2 = (const ulonglong2*)(sm + OFF_XD);
        ull* hout = (ull*)(sm + OFF_H);
        for (int jj = 0; jj < cnt; jj++) {
            const int j = j0 + jj;
            ulonglong2 x01 = xd2[j * 4 + 0];
            ulonglong2 x23 = xd2[j * 4 + 1];
            ulonglong2 x45 = xd2[j * 4 + 2];
            ulonglong2 x67 = xd2[j * 4 + 3];   // .y is pad
            ull acc = 0ull;
            ffma2(acc, x01.x, w[0]); ffma2(acc, x01.y, w[1]);
            ffma2(acc, x23.x, w[2]); ffma2(acc, x23.y, w[3]);
            ffma2(acc, x45.x, w[4]); ffma2(acc, x45.y, w[5]);
            ffma2(acc, x67.x, w[6]);
            hout[(hh * Jn + j) * 32 + lane] = acc;
            if (lane == 0) {
                float xs0 = unpk(x01.x).x, xs1 = unpk(x01.y).x;
                float xs2 = unpk(x23.x).x, xs3 = unpk(x23.y).x;
                float xs4 = unpk(x45.x).x, xs5 = unpk(x45.y).x;
                float xs6 = unpk(x67.x).x;
                float f1 = xs0 * wa1[0] + xs1 * wa1[1] + xs2 * wa1[2] + xs3 * wa1[3]
                         + xs4 * wa1[4] + xs5 * wa1[5] + xs6 * wa1[6];
                float f2 = xs0 * wa2[0] + xs1 * wa2[1] + xs2 * wa2[2] + xs3 * wa2[3]
                         + xs4 * wa2[4] + xs5 * wa2[5] + xs6 * wa2[6];
                sm[OFF_F1 + hh * Jn + j] = f1;
                sm[OFF_F2 + hh * Jn + j] = f2;
            }
        }
    }
    __syncthreads();

    // ---------------- Phase 2a: per-row softmax, float4 row writes ----------------
    if (tid < Hn * Jn) {
        const int hh = tid / Jn;
        const float fi = sm[OFF_F1 + tid];
        const float* f2r = sm + OFF_F2 + hh * Jn;
        float ebuf[Jn];
        float m = -1e30f;
        #pragma unroll
        for (int j = 0; j < Jn; j++) {
            float e = fi + f2r[j];
            e = e > 0.f ? e : 0.2f * e;
            ebuf[j] = e;
            m = fmaxf(m, e);
        }
        float s = 0.f;
        #pragma unroll
        for (int j = 0; j < Jn; j++) { float t = __expf(ebuf[j] - m); ebuf[j] = t; s += t; }
        float inv = 1.f / s;
        float* arow = sm + OFF_ATTN + tid * ATT_LD;
        #pragma unroll
        for (int q = 0; q < 5; q++)
            ((float4*)arow)[q] = make_float4(ebuf[4 * q] * inv, ebuf[4 * q + 1] * inv,
                                             ebuf[4 * q + 2] * inv, ebuf[4 * q + 3] * inv);
        arow[20] = ebuf[20] * inv;
    }
    __syncthreads();

    // ---------------- Phase 2b: hp = elu(attn @ h) -> hpT[k][i], i-quad float4 stores ----------------
    {
        const int hh = wid >> 1;
        const int ihalf = wid & 1;
        ull hvec[Jn];
        const ull* hbase = (const ull*)(sm + OFF_H) + hh * Jn * 32 + lane;
        #pragma unroll
        for (int j = 0; j < Jn; j++) hvec[j] = hbase[j * 32];

        const float* atbase = sm + OFF_ATTN + hh * Jn * ATT_LD;
        float* row_a = sm + OFF_HPT + (hh * HDn + lane) * HPT_LD;
        float* row_b = row_a + 32 * HPT_LD;
        const int q0 = ihalf ? 3 : 0;
        const int qn = ihalf ? 2 : 3;
        for (int qq = 0; qq < qn; qq++) {
            const int i = (q0 + qq) * 4;
            ull a0 = att_dot(atbase + i * ATT_LD, hvec);
            ull a1 = att_dot(atbase + (i + 1) * ATT_LD, hvec);
            ull a2 = att_dot(atbase + (i + 2) * ATT_LD, hvec);
            ull a3 = att_dot(atbase + (i + 3) * ATT_LD, hvec);
            float2 e0 = unpk(a0), e1 = unpk(a1), e2 = unpk(a2), e3 = unpk(a3);
            *(float4*)(row_a + i) = make_float4(elu1(e0.x), elu1(e1.x), elu1(e2.x), elu1(e3.x));
            *(float4*)(row_b + i) = make_float4(elu1(e0.y), elu1(e1.y), elu1(e2.y), elu1(e3.y));
        }
        if (ihalf) {   // i = 20
            ull a0 = att_dot(atbase + 20 * ATT_LD, hvec);
            float2 e0 = unpk(a0);
            row_a[20] = elu1(e0.x);
            row_b[20] = elu1(e0.y);
        }
    }
    __syncthreads();

    // ---------------- Phase 3: h2 = hp @ W_out, 8 k-slices x all 21 j, staged loads (no spill) ----------------
    {
        const int kh = wid;                // 32 k per warp
        const float* wp = W_out + (kh * 32) * HDn + lane;
        const float* hrow = sm + OFF_HPT + (kh * 32) * HPT_LD;
        ull acc[10][2];
        #pragma unroll
        for (int q = 0; q < 10; q++) { acc[q][0] = 0ull; acc[q][1] = 0ull; }
        float a20a = 0.f, a20b = 0.f;
        #pragma unroll 1
        for (int k = 0; k < 32; k++) {
            float wa = __ldcg(wp), wb = __ldcg(wp + 32);
            wp += HDn;
            ull uwa = dup2(wa), uwb = dup2(wb);
            // group 1: j0..11
            {
                ulonglong2 p0 = *(const ulonglong2*)(hrow);        // j0..3
                ulonglong2 p1 = *(const ulonglong2*)(hrow + 4);    // j4..7
                ulonglong2 p2 = *(const ulonglong2*)(hrow + 8);    // j8..11
                ffma2(acc[0][0], p0.x, uwa); ffma2(acc[0][1], p0.x, uwb);
                ffma2(acc[1][0], p0.y, uwa); ffma2(acc[1][1], p0.y, uwb);
                ffma2(acc[2][0], p1.x, uwa); ffma2(acc[2][1], p1.x, uwb);
                ffma2(acc[3][0], p1.y, uwa); ffma2(acc[3][1], p1.y, uwb);
                ffma2(acc[4][0], p2.x, uwa); ffma2(acc[4][1], p2.x, uwb);
                ffma2(acc[5][0], p2.y, uwa); ffma2(acc[5][1], p2.y, uwb);
            }
            // group 2: j12..20
            {
                ulonglong2 p3 = *(const ulonglong2*)(hrow + 12);   // j12..15
                ulonglong2 p4 = *(const ulonglong2*)(hrow + 16);   // j16..19
                float h20 = hrow[20];
                ffma2(acc[6][0], p3.x, uwa); ffma2(acc[6][1], p3.x, uwb);
                ffma2(acc[7][0], p3.y, uwa); ffma2(acc[7][1], p3.y, uwb);
                ffma2(acc[8][0], p4.x, uwa); ffma2(acc[8][1], p4.x, uwb);
                ffma2(acc[9][0], p4.y, uwa); ffma2(acc[9][1], p4.y, uwb);
                a20a = fmaf(h20, wa, a20a);
                a20b = fmaf(h20, wb, a20b);
            }
            hrow += HPT_LD;
        }

        // Stage A: warps 0-3 store their slices to RED (aliases dead h)
        if (wid < 4) {
            float* RED = sm + OFF_H + wid * (Jn * HDn);
            #pragma unroll
            for (int q = 0; q < 10; q++) {
                float2 va = unpk(acc[q][0]);
                float2 vb = unpk(acc[q][1]);
                RED[(2 * q) * 64 + lane]          = va.x;
                RED[(2 * q + 1) * 64 + lane]      = va.y;
                RED[(2 * q) * 64 + lane + 32]     = vb.x;
                RED[(2 * q + 1) * 64 + lane + 32] = vb.y;
            }
            RED[20 * 64 + lane]      = a20a;
            RED[20 * 64 + lane + 32] = a20b;
        }
        __syncthreads();
        // Stage B: warps 4-7 add in place
        if (wid >= 4) {
            float* RED = sm + OFF_H + (wid - 4) * (Jn * HDn);
            #pragma unroll
            for (int q = 0; q < 10; q++) {
                float2 va = unpk(acc[q][0]);
                float2 vb = unpk(acc[q][1]);
                RED[(2 * q) * 64 + lane]          += va.x;
                RED[(2 * q + 1) * 64 + lane]      += va.y;
                RED[(2 * q) * 64 + lane + 32]     += vb.x;
                RED[(2 * q + 1) * 64 + lane + 32] += vb.y;
            }
            RED[20 * 64 + lane]      += a20a;
            RED[20 * 64 + lane + 32] += a20b;
        }
    }
    __syncthreads();

    // ---------------- Phase 3r (+4a): reduce 4 slices -> h2; f1b/f2b via shuffles ----------------
    {
        const ull* RED = (const ull*)(sm + OFF_H);   // [4][672] ull (consecutive-d pairs)
        const float2 ao1 = make_float2(__ldg(a_out + 2 * lane), __ldg(a_out + 2 * lane + 1));
        const float2 ao2 = make_float2(__ldg(a_out + 64 + 2 * lane), __ldg(a_out + 64 + 2 * lane + 1));
        ull* h2 = (ull*)(sm + OFF_H2);
        #pragma unroll
        for (int it = 0; it < 3; it++) {
            const int s = tid + it * 256;           // slot = j*32 + t
            if (s < Jn * 32) {                      // warp-uniform (672 % 32 == 0)
                ull v = RED[s];
                fadd2(v, v, RED[s + 672]);
                ull v2; fadd2(v2, RED[s + 1344], RED[s + 2016]);
                fadd2(v, v, v2);
                h2[s] = v;
                float2 vf = unpk(v);
                float p1 = vf.x * ao1.x + vf.y * ao1.y;
                float p2 = vf.x * ao2.x + vf.y * ao2.y;
                warp_sum2(p1, p2);
                if (lane == 0) {
                    sm[OFF_F1B + (s >> 5)] = p1;
                    sm[OFF_F2B + (s >> 5)] = p2;
                }
            }
        }
    }
    __syncthreads();

    // ---------------- Phase 4b: second softmax -> AT2 (aliases ATTN), float4 writes ----------------
    if (tid < Jn) {
        const float fi = sm[OFF_F1B + tid];
        float ebuf[Jn];
        float m = -1e30f;
        #pragma unroll
        for (int j = 0; j < Jn; j++) {
            float e = fi + sm[OFF_F2B + j];
            e = e > 0.f ? e : 0.2f * e;
            ebuf[j] = e;
            m = fmaxf(m, e);
        }
        float s = 0.f;
        #pragma unroll
        for (int j = 0; j < Jn; j++) { float t = __expf(ebuf[j] - m); ebuf[j] = t; s += t; }
        float inv = 1.f / s;
        float* arow = sm + OFF_AT2 + tid * ATT_LD;
        #pragma unroll
        for (int q = 0; q < 5; q++)
            ((float4*)arow)[q] = make_float4(ebuf[4 * q] * inv, ebuf[4 * q + 1] * inv,
                                             ebuf[4 * q + 2] * inv, ebuf[4 * q + 3] * inv);
        arow[20] = ebuf[20] * inv;
    }
    __syncthreads();

    // ---------------- Phase 4c+4d fused: row = elu(attn2 @ h2); log_softmax; write out ----------------
    {
        ull h2v[Jn];
        const ull* h2b = (const ull*)(sm + OFF_H2) + lane;
        #pragma unroll
        for (int j = 0; j < Jn; j++) h2v[j] = h2b[j * 32];
        for (int i = wid; i < Jn; i += 8) {
            ull acc = att_dot(sm + OFF_AT2 + i * ATT_LD, h2v);
            float2 e = unpk(acc);
            float vx = elu1(e.x), vy = elu1(e.y);
            float m = warp_max(fmaxf(vx, vy));
            float s = warp_sum(__expf(vx - m) + __expf(vy - m));
            float lse = m + __logf(s);
            ull* op = (ull*)(out + (long long)pair * (Jn * HDn) + i * HDn);
            op[lane] = pack2(vx - lse, vy - lse);
        }
    }
}

extern "C" void kernel_launch(void* const* d_in, const int* in_sizes, int n_in,
                              void* d_out, int out_size)
{
    const float* inp = (const float*)d_in[0];
    // d_in[1] = seq_start_end (unused by the reference computation)
    const float* Wh  = (const float*)d_in[2];
    const float* ah  = (const float*)d_in[3];
    const float* Wo  = (const float*)d_in[4];
    const float* ao  = (const float*)d_in[5];
    float* out = (float*)d_out;

    const int npairs = in_sizes[0] / (Jn * NHn);   // 16*1024 = 16384

    cudaFuncSetAttribute(gat_kernel, cudaFuncAttributeMaxDynamicSharedMemorySize, SMEM_BYTES);
    gat_kernel<<<npairs, NTHREADS, SMEM_BYTES>>>(inp, Wh, ah, Wo, ao, out);
}

// round 16
// speedup vs baseline: 1.1002x; 1.1002x over previous
#include <cuda_runtime.h>
#include <math.h>

#define Jn 21
#define NHn 7
#define Hn 4
#define HDn 64
#define NTHREADS 256
#define HPT_LD 28
#define ATT_LD 28

typedef unsigned long long ull;

// ---- shared memory layout (float offsets) ----
constexpr int OFF_H    = 0;                              // 4*21*64 = 5376 (alias: RED partials in ph3)
constexpr int OFF_HPT  = OFF_H + Hn * Jn * HDn;          // 256*28  = 7168
constexpr int OFF_ATTN = OFF_HPT + 256 * HPT_LD;         // 4*21*28 = 2352 (alias: AT2 in ph4b)
constexpr int OFF_XD   = OFF_ATTN + Hn * Jn * ATT_LD;    // 21*8*2  = 336 (dup f2)
constexpr int OFF_F1   = OFF_XD + Jn * 8 * 2;            // 84
constexpr int OFF_F2   = OFF_F1 + Hn * Jn;               // 84
constexpr int OFF_H2   = OFF_F2 + Hn * Jn;               // 21*64 = 1344
constexpr int OFF_F1B  = OFF_H2 + Jn * HDn;              // 21
constexpr int OFF_F2B  = OFF_F1B + Jn;                   // 21
constexpr int OFF_AT2  = OFF_ATTN;                       // alias (ATTN dead after ph2b)
constexpr int SMEM_FLOATS = OFF_F2B + Jn;                // 16786
constexpr int SMEM_BYTES  = SMEM_FLOATS * 4;             // ~67.1 KB -> 3 CTAs/SM (201 KB)

static_assert(OFF_HPT % 4 == 0 && OFF_ATTN % 4 == 0 && OFF_XD % 4 == 0, "align16");
static_assert(Hn * Jn * HDn == 4 * Jn * 64, "RED fits H exactly");

__device__ __forceinline__ void ffma2(ull& d, ull a, ull b) {
    asm("fma.rn.f32x2 %0, %1, %2, %3;" : "=l"(d) : "l"(a), "l"(b), "l"(d));
}
__device__ __forceinline__ void fadd2(ull& d, ull a, ull b) {
    asm("add.rn.f32x2 %0, %1, %2;" : "=l"(d) : "l"(a), "l"(b));
}
__device__ __forceinline__ ull dup2(float x) {
    ull r; unsigned xi = __float_as_uint(x);
    asm("mov.b64 %0, {%1, %1};" : "=l"(r) : "r"(xi));
    return r;
}
__device__ __forceinline__ ull pack2(float a, float b) {
    ull r;
    asm("mov.b64 %0, {%1, %2};" : "=l"(r) : "f"(a), "f"(b));
    return r;
}
__device__ __forceinline__ float2 unpk(ull v) {
    float2 r;
    asm("mov.b64 {%0, %1}, %2;" : "=f"(r.x), "=f"(r.y) : "l"(v));
    return r;
}
__device__ __forceinline__ float warp_sum(float v) {
    #pragma unroll
    for (int o = 16; o > 0; o >>= 1) v += __shfl_xor_sync(0xffffffffu, v, o);
    return v;
}
__device__ __forceinline__ float warp_max(float v) {
    #pragma unroll
    for (int o = 16; o > 0; o >>= 1) v = fmaxf(v, __shfl_xor_sync(0xffffffffu, v, o));
    return v;
}
__device__ __forceinline__ void warp_sum2(float& a, float& b) {
    #pragma unroll
    for (int o = 16; o > 0; o >>= 1) {
        a += __shfl_xor_sync(0xffffffffu, a, o);
        b += __shfl_xor_sync(0xffffffffu, b, o);
    }
}
__device__ __forceinline__ float elu1(float x) {
    return x > 0.f ? x : (__expf(x) - 1.f);
}

// one attention row (21 coeffs, broadcast) dotted against 21 register-held packed vectors
__device__ __forceinline__ ull att_dot(const float* atp, const ull* hv) {
    const float4* at = (const float4*)atp;
    ull acc = 0ull;
    #pragma unroll
    for (int q = 0; q < 5; q++) {
        float4 a4 = at[q];
        ffma2(acc, dup2(a4.x), hv[q * 4 + 0]);
        ffma2(acc, dup2(a4.y), hv[q * 4 + 1]);
        ffma2(acc, dup2(a4.z), hv[q * 4 + 2]);
        ffma2(acc, dup2(a4.w), hv[q * 4 + 3]);
    }
    ffma2(acc, dup2(atp[20]), hv[20]);
    return acc;
}

__global__ void __launch_bounds__(NTHREADS, 3)
gat_kernel(const float* __restrict__ inp,
           const float* __restrict__ W_heads,
           const float* __restrict__ a_heads,
           const float* __restrict__ W_out,
           const float* __restrict__ a_out,
           float* __restrict__ out)
{
    extern __shared__ float sm[];
    const int tid  = threadIdx.x;
    const int lane = tid & 31;
    const int wid  = tid >> 5;
    const int pair = blockIdx.x;

    // ---------------- Phase 0: stage x (reshaped, duplicated for f32x2) ----------------
    {
        const float* ip = inp + (long long)pair * (Jn * NHn);
        if (tid < Jn * NHn) {
            float v = ip[tid];
            int j, c;
            if (tid < Jn * 3)          { j = tid / 3;          c = tid % 3; }
            else if (tid < 2 * Jn * 3) { int t = tid - Jn * 3; j = t / 3;  c = 3 + t % 3; }
            else                       { j = tid - 2 * Jn * 3; c = 6; }
            ((float2*)(sm + OFF_XD))[j * 8 + c] = make_float2(v, v);
        }
        if (tid < Jn)   // zero pad slot c=7
            ((float2*)(sm + OFF_XD))[tid * 8 + 7] = make_float2(0.f, 0.f);
    }
    __syncthreads();

    // ---------------- Phase 1 (+1b): h = x @ Wh ; f1/f2 = x @ (Wh@a) ----------------
    {
        const int hh = wid >> 1;           // head
        const int jh = wid & 1;            // j-half
        const float* wg = W_heads + hh * (NHn * HDn) + lane;
        ull w[NHn];
        #pragma unroll
        for (int n = 0; n < NHn; n++)
            w[n] = pack2(__ldg(wg + n * HDn), __ldg(wg + n * HDn + 32));
        const float2 a1f = make_float2(__ldg(a_heads + hh * 128 + lane),
                                       __ldg(a_heads + hh * 128 + lane + 32));
        const float2 a2f = make_float2(__ldg(a_heads + hh * 128 + 64 + lane),
                                       __ldg(a_heads + hh * 128 + 64 + lane + 32));
        float wa1[NHn], wa2[NHn];
        #pragma unroll
        for (int n = 0; n < NHn; n++) {
            float2 wf = unpk(w[n]);
            float p1 = wf.x * a1f.x + wf.y * a1f.y;
            float p2 = wf.x * a2f.x + wf.y * a2f.y;
            warp_sum2(p1, p2);
            wa1[n] = p1; wa2[n] = p2;
        }

        const int j0 = jh * 11, cnt = 11 - jh;
        const ulonglong2* xd2 = (const ulonglong2*)(sm + OFF_XD);
        ull* hout = (ull*)(sm + OFF_H);
        for (int jj = 0; jj < cnt; jj++) {
            const int j = j0 + jj;
            ulonglong2 x01 = xd2[j * 4 + 0];
            ulonglong2 x23 = xd2[j * 4 + 1];
            ulonglong2 x45 = xd2[j * 4 + 2];
            ulonglong2 x67 = xd2[j * 4 + 3];   // .y is pad
            ull acc = 0ull;
            ffma2(acc, x01.x, w[0]); ffma2(acc, x01.y, w[1]);
            ffma2(acc, x23.x, w[2]); ffma2(acc, x23.y, w[3]);
            ffma2(acc, x45.x, w[4]); ffma2(acc, x45.y, w[5]);
            ffma2(acc, x67.x, w[6]);
            hout[(hh * Jn + j) * 32 + lane] = acc;
            if (lane == 0) {
                float xs0 = unpk(x01.x).x, xs1 = unpk(x01.y).x;
                float xs2 = unpk(x23.x).x, xs3 = unpk(x23.y).x;
                float xs4 = unpk(x45.x).x, xs5 = unpk(x45.y).x;
                float xs6 = unpk(x67.x).x;
                float f1 = xs0 * wa1[0] + xs1 * wa1[1] + xs2 * wa1[2] + xs3 * wa1[3]
                         + xs4 * wa1[4] + xs5 * wa1[5] + xs6 * wa1[6];
                float f2 = xs0 * wa2[0] + xs1 * wa2[1] + xs2 * wa2[2] + xs3 * wa2[3]
                         + xs4 * wa2[4] + xs5 * wa2[5] + xs6 * wa2[6];
                sm[OFF_F1 + hh * Jn + j] = f1;
                sm[OFF_F2 + hh * Jn + j] = f2;
            }
        }
    }
    __syncthreads();

    // ---------------- Phase 2a: per-row softmax, float4 row writes ----------------
    if (tid < Hn * Jn) {
        const int hh = tid / Jn;
        const float fi = sm[OFF_F1 + tid];
        const float* f2r = sm + OFF_F2 + hh * Jn;
        float ebuf[Jn];
        float m = -1e30f;
        #pragma unroll
        for (int j = 0; j < Jn; j++) {
            float e = fi + f2r[j];
            e = e > 0.f ? e : 0.2f * e;
            ebuf[j] = e;
            m = fmaxf(m, e);
        }
        float s = 0.f;
        #pragma unroll
        for (int j = 0; j < Jn; j++) { float t = __expf(ebuf[j] - m); ebuf[j] = t; s += t; }
        float inv = 1.f / s;
        float* arow = sm + OFF_ATTN + tid * ATT_LD;
        #pragma unroll
        for (int q = 0; q < 5; q++)
            ((float4*)arow)[q] = make_float4(ebuf[4 * q] * inv, ebuf[4 * q + 1] * inv,
                                             ebuf[4 * q + 2] * inv, ebuf[4 * q + 3] * inv);
        arow[20] = ebuf[20] * inv;
    }
    __syncthreads();

    // ---------------- Phase 2b: hp = elu(attn @ h) -> hpT[k][i], i-quad float4 stores ----------------
    {
        const int hh = wid >> 1;
        const int ihalf = wid & 1;
        ull hvec[Jn];
        const ull* hbase = (const ull*)(sm + OFF_H) + hh * Jn * 32 + lane;
        #pragma unroll
        for (int j = 0; j < Jn; j++) hvec[j] = hbase[j * 32];

        const float* atbase = sm + OFF_ATTN + hh * Jn * ATT_LD;
        float* row_a = sm + OFF_HPT + (hh * HDn + lane) * HPT_LD;
        float* row_b = row_a + 32 * HPT_LD;
        const int q0 = ihalf ? 3 : 0;
        const int qn = ihalf ? 2 : 3;
        for (int qq = 0; qq < qn; qq++) {
            const int i = (q0 + qq) * 4;
            ull a0 = att_dot(atbase + i * ATT_LD, hvec);
            ull a1 = att_dot(atbase + (i + 1) * ATT_LD, hvec);
            ull a2 = att_dot(atbase + (i + 2) * ATT_LD, hvec);
            ull a3 = att_dot(atbase + (i + 3) * ATT_LD, hvec);
            float2 e0 = unpk(a0), e1 = unpk(a1), e2 = unpk(a2), e3 = unpk(a3);
            *(float4*)(row_a + i) = make_float4(elu1(e0.x), elu1(e1.x), elu1(e2.x), elu1(e3.x));
            *(float4*)(row_b + i) = make_float4(elu1(e0.y), elu1(e1.y), elu1(e2.y), elu1(e3.y));
        }
        if (ihalf) {   // i = 20
            ull a0 = att_dot(atbase + 20 * ATT_LD, hvec);
            float2 e0 = unpk(a0);
            row_a[20] = elu1(e0.x);
            row_b[20] = elu1(e0.y);
        }
    }
    __syncthreads();

    // ---------------- Phase 3: h2 = hp @ W_out, 8 k-slices x all 21 j ----------------
    // hp rows loaded with ld.volatile.shared into a reused register pair: ptxas cannot
    // hoist/rename them, so at most one 16B load is in flight -> no spill at 80 regs.
    {
        const int kh = wid;                // 32 k per warp
        const float* wp = W_out + (kh * 32) * HDn + lane;
        unsigned hs = (unsigned)__cvta_generic_to_shared(sm + OFF_HPT + (kh * 32) * HPT_LD);
        ull acc[10][2];
        #pragma unroll
        for (int q = 0; q < 10; q++) { acc[q][0] = 0ull; acc[q][1] = 0ull; }
        float a20a = 0.f, a20b = 0.f;
        #pragma unroll 2
        for (int k = 0; k < 32; k++) {
            float wa = __ldcg(wp), wb = __ldcg(wp + 32);
            wp += HDn;
            ull uwa = dup2(wa), uwb = dup2(wb);
            ull x0, x1;
            asm volatile("ld.volatile.shared.v2.u64 {%0,%1}, [%2];"
                         : "=l"(x0), "=l"(x1) : "r"(hs));
            ffma2(acc[0][0], x0, uwa); ffma2(acc[0][1], x0, uwb);
            ffma2(acc[1][0], x1, uwa); ffma2(acc[1][1], x1, uwb);
            asm volatile("ld.volatile.shared.v2.u64 {%0,%1}, [%2];"
                         : "=l"(x0), "=l"(x1) : "r"(hs + 16));
            ffma2(acc[2][0], x0, uwa); ffma2(acc[2][1], x0, uwb);
            ffma2(acc[3][0], x1, uwa); ffma2(acc[3][1], x1, uwb);
            asm volatile("ld.volatile.shared.v2.u64 {%0,%1}, [%2];"
                         : "=l"(x0), "=l"(x1) : "r"(hs + 32));
            ffma2(acc[4][0], x0, uwa); ffma2(acc[4][1], x0, uwb);
            ffma2(acc[5][0], x1, uwa); ffma2(acc[5][1], x1, uwb);
            asm volatile("ld.volatile.shared.v2.u64 {%0,%1}, [%2];"
                         : "=l"(x0), "=l"(x1) : "r"(hs + 48));
            ffma2(acc[6][0], x0, uwa); ffma2(acc[6][1], x0, uwb);
            ffma2(acc[7][0], x1, uwa); ffma2(acc[7][1], x1, uwb);
            asm volatile("ld.volatile.shared.v2.u64 {%0,%1}, [%2];"
                         : "=l"(x0), "=l"(x1) : "r"(hs + 64));
            ffma2(acc[8][0], x0, uwa); ffma2(acc[8][1], x0, uwb);
            ffma2(acc[9][0], x1, uwa); ffma2(acc[9][1], x1, uwb);
            float h20;
            asm volatile("ld.volatile.shared.f32 %0, [%1];"
                         : "=f"(h20) : "r"(hs + 80));
            a20a = fmaf(h20, wa, a20a);
            a20b = fmaf(h20, wb, a20b);
            hs += HPT_LD * 4;
        }

        // Stage A: warps 0-3 store their slices to RED (aliases dead h)
        if (wid < 4) {
            float* RED = sm + OFF_H + wid * (Jn * HDn);
            #pragma unroll
            for (int q = 0; q < 10; q++) {
                float2 va = unpk(acc[q][0]);
                float2 vb = unpk(acc[q][1]);
                RED[(2 * q) * 64 + lane]          = va.x;
                RED[(2 * q + 1) * 64 + lane]      = va.y;
                RED[(2 * q) * 64 + lane + 32]     = vb.x;
                RED[(2 * q + 1) * 64 + lane + 32] = vb.y;
            }
            RED[20 * 64 + lane]      = a20a;
            RED[20 * 64 + lane + 32] = a20b;
        }
        __syncthreads();
        // Stage B: warps 4-7 add in place
        if (wid >= 4) {
            float* RED = sm + OFF_H + (wid - 4) * (Jn * HDn);
            #pragma unroll
            for (int q = 0; q < 10; q++) {
                float2 va = unpk(acc[q][0]);
                float2 vb = unpk(acc[q][1]);
                RED[(2 * q) * 64 + lane]          += va.x;
                RED[(2 * q + 1) * 64 + lane]      += va.y;
                RED[(2 * q) * 64 + lane + 32]     += vb.x;
                RED[(2 * q + 1) * 64 + lane + 32] += vb.y;
            }
            RED[20 * 64 + lane]      += a20a;
            RED[20 * 64 + lane + 32] += a20b;
        }
    }
    __syncthreads();

    // ---------------- Phase 3r (+4a): reduce 4 slices -> h2; f1b/f2b via shuffles ----------------
    {
        const ull* RED = (const ull*)(sm + OFF_H);   // [4][672] ull (consecutive-d pairs)
        const float2 ao1 = make_float2(__ldg(a_out + 2 * lane), __ldg(a_out + 2 * lane + 1));
        const float2 ao2 = make_float2(__ldg(a_out + 64 + 2 * lane), __ldg(a_out + 64 + 2 * lane + 1));
        ull* h2 = (ull*)(sm + OFF_H2);
        #pragma unroll
        for (int it = 0; it < 3; it++) {
            const int s = tid + it * 256;           // slot = j*32 + t
            if (s < Jn * 32) {                      // warp-uniform (672 % 32 == 0)
                ull v = RED[s];
                fadd2(v, v, RED[s + 672]);
                ull v2; fadd2(v2, RED[s + 1344], RED[s + 2016]);
                fadd2(v, v, v2);
                h2[s] = v;
                float2 vf = unpk(v);
                float p1 = vf.x * ao1.x + vf.y * ao1.y;
                float p2 = vf.x * ao2.x + vf.y * ao2.y;
                warp_sum2(p1, p2);
                if (lane == 0) {
                    sm[OFF_F1B + (s >> 5)] = p1;
                    sm[OFF_F2B + (s >> 5)] = p2;
                }
            }
        }
    }
    __syncthreads();

    // ---------------- Phase 4b: second softmax -> AT2 (aliases ATTN), float4 writes ----------------
    if (tid < Jn) {
        const float fi = sm[OFF_F1B + tid];
        float ebuf[Jn];
        float m = -1e30f;
        #pragma unroll
        for (int j = 0; j < Jn; j++) {
            float e = fi + sm[OFF_F2B + j];
            e = e > 0.f ? e : 0.2f * e;
            ebuf[j] = e;
            m = fmaxf(m, e);
        }
        float s = 0.f;
        #pragma unroll
        for (int j = 0; j < Jn; j++) { float t = __expf(ebuf[j] - m); ebuf[j] = t; s += t; }
        float inv = 1.f / s;
        float* arow = sm + OFF_AT2 + tid * ATT_LD;
        #pragma unroll
        for (int q = 0; q < 5; q++)
            ((float4*)arow)[q] = make_float4(ebuf[4 * q] * inv, ebuf[4 * q + 1] * inv,
                                             ebuf[4 * q + 2] * inv, ebuf[4 * q + 3] * inv);
        arow[20] = ebuf[20] * inv;
    }
    __syncthreads();

    // ---------------- Phase 4c+4d fused: row = elu(attn2 @ h2); log_softmax; write out ----------------
    {
        ull h2v[Jn];
        const ull* h2b = (const ull*)(sm + OFF_H2) + lane;
        #pragma unroll
        for (int j = 0; j < Jn; j++) h2v[j] = h2b[j * 32];
        for (int i = wid; i < Jn; i += 8) {
            ull acc = att_dot(sm + OFF_AT2 + i * ATT_LD, h2v);
            float2 e = unpk(acc);
            float vx = elu1(e.x), vy = elu1(e.y);
            float m = warp_max(fmaxf(vx, vy));
            float s = warp_sum(__expf(vx - m) + __expf(vy - m));
            float lse = m + __logf(s);
            ull* op = (ull*)(out + (long long)pair * (Jn * HDn) + i * HDn);
            op[lane] = pack2(vx - lse, vy - lse);
        }
    }
}

extern "C" void kernel_launch(void* const* d_in, const int* in_sizes, int n_in,
                              void* d_out, int out_size)
{
    const float* inp = (const float*)d_in[0];
    // d_in[1] = seq_start_end (unused by the reference computation)
    const float* Wh  = (const float*)d_in[2];
    const float* ah  = (const float*)d_in[3];
    const float* Wo  = (const float*)d_in[4];
    const float* ao  = (const float*)d_in[5];
    float* out = (float*)d_out;

    const int npairs = in_sizes[0] / (Jn * NHn);   // 16*1024 = 16384

    cudaFuncSetAttribute(gat_kernel, cudaFuncAttributeMaxDynamicSharedMemorySize, SMEM_BYTES);
    gat_kernel<<<npairs, NTHREADS, SMEM_BYTES>>>(inp, Wh, ah, Wo, ao, out);
}